// round 11
// baseline (speedup 1.0000x reference)
#include <cuda_runtime.h>
#include <cstdint>

// LWTA over groups of 4 consecutive fp32 units. One v8 (256-bit) = 2 groups.
// Keep first max (strict > matches jnp.argmax first-tie semantics), zero rest.
//
// Winning config (R10) + streaming cache hints: sm_103a 256-bit global
// ld/st (LDG.E.256/STG.E.256) with .cs (evict-first) — zero-reuse stream,
// so don't let the write-allocate stream fight the read stream in L2.
// 256 threads, 2 x v8 per thread (64B), grid 8192, exact cover. regs ~27.
// R10 measured: 43.52us wall / 36.4us kernel — best of all configs; the
// halved LSU dispatch rate vs float4 relieved the L1tex/issue path.

__device__ __forceinline__ void ldg256cs(const float* p, uint32_t* v) {
    asm volatile("ld.global.cs.v8.b32 {%0,%1,%2,%3,%4,%5,%6,%7}, [%8];"
                 : "=r"(v[0]), "=r"(v[1]), "=r"(v[2]), "=r"(v[3]),
                   "=r"(v[4]), "=r"(v[5]), "=r"(v[6]), "=r"(v[7])
                 : "l"(p));
}

__device__ __forceinline__ void stg256cs(float* p, const uint32_t* v) {
    asm volatile("st.global.cs.v8.b32 [%0], {%1,%2,%3,%4,%5,%6,%7,%8};"
                 :: "l"(p),
                    "r"(v[0]), "r"(v[1]), "r"(v[2]), "r"(v[3]),
                    "r"(v[4]), "r"(v[5]), "r"(v[6]), "r"(v[7])
                 : "memory");
}

// LWTA on one group of 4 fp32 values held as uint bits, in place.
__device__ __forceinline__ void lwta_group(uint32_t* g) {
    float f0 = __uint_as_float(g[0]);
    float f1 = __uint_as_float(g[1]);
    float f2 = __uint_as_float(g[2]);
    float f3 = __uint_as_float(g[3]);
    float m = f0; int idx = 0;
    if (f1 > m) { m = f1; idx = 1; }
    if (f2 > m) { m = f2; idx = 2; }
    if (f3 > m) { m = f3; idx = 3; }
    g[0] = (idx == 0) ? g[0] : 0u;
    g[1] = (idx == 1) ? g[1] : 0u;
    g[2] = (idx == 2) ? g[2] : 0u;
    g[3] = (idx == 3) ? g[3] : 0u;
}

__global__ void __launch_bounds__(256) lwta_kernel(const float* __restrict__ in,
                                                   float* __restrict__ out,
                                                   int n) {
    const int BS = 256;
    const int PER_BLOCK = BS * 16;               // 4096 floats per block
    int block_base = blockIdx.x * PER_BLOCK;

    if (block_base + PER_BLOCK <= n) {
        int i0 = block_base + threadIdx.x * 8;   // segment 0
        int i1 = i0 + BS * 8;                    // segment 1 (+2048 floats)
        uint32_t a[8], b[8];
        ldg256cs(in + i0, a);
        ldg256cs(in + i1, b);
        lwta_group(a);
        lwta_group(a + 4);
        lwta_group(b);
        lwta_group(b + 4);
        stg256cs(out + i0, a);
        stg256cs(out + i1, b);
    } else {
        // tail: per float4 group
        for (int g = block_base + threadIdx.x * 4; g + 4 <= n; g += BS * 4) {
            uint32_t v[4];
            v[0] = __float_as_uint(in[g]);
            v[1] = __float_as_uint(in[g + 1]);
            v[2] = __float_as_uint(in[g + 2]);
            v[3] = __float_as_uint(in[g + 3]);
            lwta_group(v);
            out[g]     = __uint_as_float(v[0]);
            out[g + 1] = __uint_as_float(v[1]);
            out[g + 2] = __uint_as_float(v[2]);
            out[g + 3] = __uint_as_float(v[3]);
        }
    }
}

extern "C" void kernel_launch(void* const* d_in, const int* in_sizes, int n_in,
                              void* d_out, int out_size) {
    const float* in = (const float*)d_in[0];
    float* out = (float*)d_out;
    int n = in_sizes[0];               // 4096*8192 = 33554432 floats
    int per_block = 256 * 16;          // 4096 floats per block
    int blocks = (n + per_block - 1) / per_block;  // 8192
    lwta_kernel<<<blocks, 256>>>(in, out, n);
}

// round 12
// speedup vs baseline: 1.0217x; 1.0217x over previous
#include <cuda_runtime.h>
#include <cstdint>

// LWTA over groups of 4 consecutive fp32 units. One v8 (256-bit) = 2 groups.
// Keep first max (strict > matches jnp.argmax first-tie semantics), zero rest.
//
// FINAL (R10 config, best measured wall: 43.52us): sm_103a 256-bit global
// ld/st (LDG.E.256/STG.E.256 via ld/st.global.v8.b32), DEFAULT cache policy.
// 256 threads, 2 x v8 per thread (64B), grid 8192, exact cover, regs ~27.
//
// Convergence evidence: kernel ~36.4us = 268MB mandatory traffic @ ~7.4TB/s
// effective (~92% of 8TB/s HBM spec). Ruled out on both sides:
//  - float4 path (2x LSU dispatch): 44.7-45.5us
//  - unroll-8 float4 (regs 40, occ 60%): 44.7-45.1us
//  - 512-thread blocks (L1tex queue contention): 45.5us
//  - persistent grid-stride (loop overhead): 48.1us
//  - .cs evict-first hints: best ncu sample (35.7us) but WORST replay wall
//    (46.8us) — evict-first kills L2 write slack in graph-replay steady state.

__device__ __forceinline__ void ldg256(const float* p, uint32_t* v) {
    asm volatile("ld.global.v8.b32 {%0,%1,%2,%3,%4,%5,%6,%7}, [%8];"
                 : "=r"(v[0]), "=r"(v[1]), "=r"(v[2]), "=r"(v[3]),
                   "=r"(v[4]), "=r"(v[5]), "=r"(v[6]), "=r"(v[7])
                 : "l"(p));
}

__device__ __forceinline__ void stg256(float* p, const uint32_t* v) {
    asm volatile("st.global.v8.b32 [%0], {%1,%2,%3,%4,%5,%6,%7,%8};"
                 :: "l"(p),
                    "r"(v[0]), "r"(v[1]), "r"(v[2]), "r"(v[3]),
                    "r"(v[4]), "r"(v[5]), "r"(v[6]), "r"(v[7])
                 : "memory");
}

// LWTA on one group of 4 fp32 values held as uint bits, in place.
__device__ __forceinline__ void lwta_group(uint32_t* g) {
    float f0 = __uint_as_float(g[0]);
    float f1 = __uint_as_float(g[1]);
    float f2 = __uint_as_float(g[2]);
    float f3 = __uint_as_float(g[3]);
    float m = f0; int idx = 0;
    if (f1 > m) { m = f1; idx = 1; }
    if (f2 > m) { m = f2; idx = 2; }
    if (f3 > m) { m = f3; idx = 3; }
    g[0] = (idx == 0) ? g[0] : 0u;
    g[1] = (idx == 1) ? g[1] : 0u;
    g[2] = (idx == 2) ? g[2] : 0u;
    g[3] = (idx == 3) ? g[3] : 0u;
}

__global__ void __launch_bounds__(256) lwta_kernel(const float* __restrict__ in,
                                                   float* __restrict__ out,
                                                   int n) {
    const int BS = 256;
    const int PER_BLOCK = BS * 16;               // 4096 floats per block
    int block_base = blockIdx.x * PER_BLOCK;

    if (block_base + PER_BLOCK <= n) {
        int i0 = block_base + threadIdx.x * 8;   // segment 0
        int i1 = i0 + BS * 8;                    // segment 1 (+2048 floats)
        uint32_t a[8], b[8];
        ldg256(in + i0, a);
        ldg256(in + i1, b);
        lwta_group(a);
        lwta_group(a + 4);
        lwta_group(b);
        lwta_group(b + 4);
        stg256(out + i0, a);
        stg256(out + i1, b);
    } else {
        // tail: per float4 group
        for (int g = block_base + threadIdx.x * 4; g + 4 <= n; g += BS * 4) {
            uint32_t v[4];
            v[0] = __float_as_uint(in[g]);
            v[1] = __float_as_uint(in[g + 1]);
            v[2] = __float_as_uint(in[g + 2]);
            v[3] = __float_as_uint(in[g + 3]);
            lwta_group(v);
            out[g]     = __uint_as_float(v[0]);
            out[g + 1] = __uint_as_float(v[1]);
            out[g + 2] = __uint_as_float(v[2]);
            out[g + 3] = __uint_as_float(v[3]);
        }
    }
}

extern "C" void kernel_launch(void* const* d_in, const int* in_sizes, int n_in,
                              void* d_out, int out_size) {
    const float* in = (const float*)d_in[0];
    float* out = (float*)d_out;
    int n = in_sizes[0];               // 4096*8192 = 33554432 floats
    int per_block = 256 * 16;          // 4096 floats per block
    int blocks = (n + per_block - 1) / per_block;  // 8192
    lwta_kernel<<<blocks, 256>>>(in, out, n);
}

// round 14
// speedup vs baseline: 1.0758x; 1.0530x over previous
#include <cuda_runtime.h>
#include <cstdint>

// LWTA over groups of 4 consecutive fp32 units. One v8 (256-bit) = 2 groups.
// Keep first max (strict > matches jnp.argmax first-tie semantics), zero rest.
//
// FINAL: sm_103a 256-bit global ld/st (LDG.E.256/STG.E.256), default cache
// policy, 256 threads, 2 x v8 per thread (64B), grid 8192 (exact cover of
// 33554432 floats), regs ~27, every warp access 1024B contiguous.
//
// Roofline: 268MB mandatory traffic; kernel 36-39us ~= 7.0-7.4TB/s effective
// (~90% of 8TB/s HBM spec). Cross-round wall variance measured at ~+/-1.2us
// (same binary: 43.52 vs 45.79us), so remaining deltas are environmental.
// Ruled out: float4 (2x LSU dispatch), unroll-8 float4 (occ loss),
// 512-thread blocks (L1tex contention), persistent grid (loop overhead),
// .cs hints (graph-replay steady-state regression).

__device__ __forceinline__ void ldg256(const float* p, uint32_t* v) {
    asm volatile("ld.global.v8.b32 {%0,%1,%2,%3,%4,%5,%6,%7}, [%8];"
                 : "=r"(v[0]), "=r"(v[1]), "=r"(v[2]), "=r"(v[3]),
                   "=r"(v[4]), "=r"(v[5]), "=r"(v[6]), "=r"(v[7])
                 : "l"(p));
}

__device__ __forceinline__ void stg256(float* p, const uint32_t* v) {
    asm volatile("st.global.v8.b32 [%0], {%1,%2,%3,%4,%5,%6,%7,%8};"
                 :: "l"(p),
                    "r"(v[0]), "r"(v[1]), "r"(v[2]), "r"(v[3]),
                    "r"(v[4]), "r"(v[5]), "r"(v[6]), "r"(v[7])
                 : "memory");
}

// LWTA on one group of 4 fp32 values held as uint bits, in place.
__device__ __forceinline__ void lwta_group(uint32_t* g) {
    float f0 = __uint_as_float(g[0]);
    float f1 = __uint_as_float(g[1]);
    float f2 = __uint_as_float(g[2]);
    float f3 = __uint_as_float(g[3]);
    float m = f0; int idx = 0;
    if (f1 > m) { m = f1; idx = 1; }
    if (f2 > m) { m = f2; idx = 2; }
    if (f3 > m) { m = f3; idx = 3; }
    g[0] = (idx == 0) ? g[0] : 0u;
    g[1] = (idx == 1) ? g[1] : 0u;
    g[2] = (idx == 2) ? g[2] : 0u;
    g[3] = (idx == 3) ? g[3] : 0u;
}

__global__ void __launch_bounds__(256) lwta_kernel(const float* __restrict__ in,
                                                   float* __restrict__ out,
                                                   int n) {
    const int BS = 256;
    const int PER_BLOCK = BS * 16;               // 4096 floats per block
    int i0 = blockIdx.x * PER_BLOCK + threadIdx.x * 8;
    int i1 = i0 + BS * 8;
    if (i1 + 8 > n) return;                      // never taken for exact cover

    uint32_t a[8], b[8];
    ldg256(in + i0, a);
    ldg256(in + i1, b);
    lwta_group(a);
    lwta_group(a + 4);
    lwta_group(b);
    lwta_group(b + 4);
    stg256(out + i0, a);
    stg256(out + i1, b);
}

extern "C" void kernel_launch(void* const* d_in, const int* in_sizes, int n_in,
                              void* d_out, int out_size) {
    const float* in = (const float*)d_in[0];
    float* out = (float*)d_out;
    int n = in_sizes[0];               // 4096*8192 = 33554432 floats
    int per_block = 256 * 16;          // 4096 floats per block
    int blocks = (n + per_block - 1) / per_block;  // 8192, exact cover
    lwta_kernel<<<blocks, 256>>>(in, out, n);
}